// round 1
// baseline (speedup 1.0000x reference)
#include <cuda_runtime.h>

#define NN   10000
#define EE   320000
#define RR   460
#define BB   30
#define DD   200
#define KTOT (BB * DD + DD)   // 6200

// ---- device scratch (no allocations allowed) ----
__device__ float g_A[(size_t)NN * KTOT];   // [H*inv_deg | x] rows, 248 MB
__device__ int   g_deg[NN];
__device__ int   g_off[NN + 1];
__device__ int   g_cur[NN];
__device__ int   g_esrc[EE];
__device__ int   g_erel[EE];

// ---------------- CSR build ----------------
__global__ void k_zero_deg() {
    int i = blockIdx.x * blockDim.x + threadIdx.x;
    if (i < NN) g_deg[i] = 0;
}

__global__ void k_count(const int* __restrict__ eidx) {
    int e = blockIdx.x * blockDim.x + threadIdx.x;
    if (e < EE) atomicAdd(&g_deg[eidx[EE + e]], 1);
}

__global__ void k_scan() {
    __shared__ int buf[1024];
    __shared__ int carry_s;
    int tid = threadIdx.x;
    if (tid == 0) carry_s = 0;
    __syncthreads();
    for (int base = 0; base < NN; base += 1024) {
        int i = base + tid;
        int v = (i < NN) ? g_deg[i] : 0;
        buf[tid] = v;
        __syncthreads();
        for (int off = 1; off < 1024; off <<= 1) {
            int t = (tid >= off) ? buf[tid - off] : 0;
            __syncthreads();
            buf[tid] += t;
            __syncthreads();
        }
        int excl = carry_s + buf[tid] - v;
        if (i < NN) { g_off[i] = excl; g_cur[i] = excl; }
        __syncthreads();
        if (tid == 0) carry_s += buf[1023];
        __syncthreads();
    }
    if (tid == 0) g_off[NN] = carry_s;
}

__global__ void k_fill(const int* __restrict__ eidx, const int* __restrict__ etype) {
    int e = blockIdx.x * blockDim.x + threadIdx.x;
    if (e < EE) {
        int t = eidx[EE + e];
        int p = atomicAdd(&g_cur[t], 1);
        g_esrc[p] = eidx[e];
        g_erel[p] = etype[e];
    }
}

// ---------------- aggregation: H[n,b,d] = inv_deg * sum_{e->n} coeff[r_e,b]*x[src_e,d] ----------------
#define AGG_T 224
#define EB    32
__global__ __launch_bounds__(AGG_T) void k_agg(const float* __restrict__ x,
                                               const float* __restrict__ coeff) {
    __shared__ float sC[EB][BB];
    __shared__ int   sSrc[EB];
    __shared__ int   sRel[EB];
    int n   = blockIdx.x;
    int tid = threadIdx.x;
    int start = g_off[n], end = g_off[n + 1];
    int deg = end - start;
    float inv = 1.0f / (float)(deg > 1 ? deg : 1);

    float acc[BB];
#pragma unroll
    for (int b = 0; b < BB; b++) acc[b] = 0.f;

    int d = tid;
    for (int e0 = start; e0 < end; e0 += EB) {
        int nb = min(EB, end - e0);
        __syncthreads();                       // protect sC/sSrc from prior-iter readers
        for (int i = tid; i < nb; i += AGG_T) {
            sSrc[i] = g_esrc[e0 + i];
            sRel[i] = g_erel[e0 + i];
        }
        __syncthreads();
        for (int i = tid; i < nb * BB; i += AGG_T) {
            int le = i / BB, b = i - le * BB;
            sC[le][b] = coeff[sRel[le] * BB + b];
        }
        __syncthreads();
        if (d < DD) {
            for (int le = 0; le < nb; le++) {
                float xv = x[(size_t)sSrc[le] * DD + d];
#pragma unroll
                for (int b = 0; b < BB; b++) acc[b] = fmaf(sC[le][b], xv, acc[b]);
            }
        }
    }
    if (d < DD) {
        size_t row = (size_t)n * KTOT;
#pragma unroll
        for (int b = 0; b < BB; b++) g_A[row + b * DD + d] = acc[b] * inv;
        g_A[row + BB * DD + d] = x[(size_t)n * DD + d];   // self-loop K-columns
    }
}

// ---------------- GEMM: out(10000x200) = g_A(10000x6200) @ [weight;self_weight](6200x200) + bias ----------------
#define BM 40
#define BK 20
#define GT 320
__global__ __launch_bounds__(GT) void k_gemm(const float* __restrict__ weight,
                                             const float* __restrict__ selfw,
                                             const float* __restrict__ bias,
                                             float* __restrict__ out) {
    __shared__ float sA[BK][BM + 1];
    __shared__ float sB[BK][DD];
    int tid = threadIdx.x;
    int m0  = blockIdx.x * BM;
    int tr  = tid / 40;   // 0..7
    int tc  = tid % 40;   // 0..39

    float acc[5][5];
#pragma unroll
    for (int i = 0; i < 5; i++)
#pragma unroll
        for (int j = 0; j < 5; j++) acc[i][j] = 0.f;

    for (int k0 = 0; k0 < KTOT; k0 += BK) {
        // A tile: BM*BK = 800 floats
#pragma unroll
        for (int i = 0; i < 3; i++) {
            int ii = tid + i * GT;
            if (ii < BM * BK) {
                int r = ii / BK, kk = ii % BK;
                sA[kk][r] = g_A[(size_t)(m0 + r) * KTOT + k0 + kk];
            }
        }
        // B tile: BK*DD = 4000 floats; boundary at k=6000 is BK-aligned
        const float* Bsrc = (k0 < BB * DD) ? (weight + (size_t)k0 * DD)
                                           : (selfw + (size_t)(k0 - BB * DD) * DD);
#pragma unroll
        for (int i = 0; i < 13; i++) {
            int ii = tid + i * GT;
            if (ii < BK * DD) {
                int kk = ii / DD, c = ii - kk * DD;
                sB[kk][c] = Bsrc[kk * DD + c];
            }
        }
        __syncthreads();
#pragma unroll
        for (int kk = 0; kk < BK; kk++) {
            float a[5], b[5];
#pragma unroll
            for (int i = 0; i < 5; i++) a[i] = sA[kk][tr + 8 * i];
#pragma unroll
            for (int j = 0; j < 5; j++) b[j] = sB[kk][tc + 40 * j];
#pragma unroll
            for (int i = 0; i < 5; i++)
#pragma unroll
                for (int j = 0; j < 5; j++) acc[i][j] = fmaf(a[i], b[j], acc[i][j]);
        }
        __syncthreads();
    }
#pragma unroll
    for (int j = 0; j < 5; j++) {
        float bv = bias[tc + 40 * j];
#pragma unroll
        for (int i = 0; i < 5; i++)
            out[(size_t)(m0 + tr + 8 * i) * DD + tc + 40 * j] = acc[i][j] + bv;
    }
}

extern "C" void kernel_launch(void* const* d_in, const int* in_sizes, int n_in,
                              void* d_out, int out_size) {
    const float* x      = (const float*)d_in[0];
    const float* weight = (const float*)d_in[1];
    const float* coeff  = (const float*)d_in[2];
    const float* selfw  = (const float*)d_in[3];
    const float* bias   = (const float*)d_in[4];
    const int*   eidx   = (const int*)d_in[5];
    const int*   etype  = (const int*)d_in[6];
    float*       out    = (float*)d_out;

    k_zero_deg<<<(NN + 255) / 256, 256>>>();
    k_count<<<(EE + 255) / 256, 256>>>(eidx);
    k_scan<<<1, 1024>>>();
    k_fill<<<(EE + 255) / 256, 256>>>(eidx, etype);
    k_agg<<<NN, AGG_T>>>(x, coeff);
    k_gemm<<<NN / BM, GT>>>(weight, selfw, bias, out);
}